// round 8
// baseline (speedup 1.0000x reference)
#include <cuda_runtime.h>
#include <stdint.h>

// Problem constants (from reference_code)
#define B_DIM    16
#define C_DIM    23
#define T_DIM    120200
#define P_DIM    1000
#define PS_DIM   200
#define STRIDE_  150
#define ACTUAL_  801           // min((T-PS)/STRIDE + 1, MAX_PATCHES)

#define BC_DIM   (B_DIM * C_DIM)                 // 368
#define V4       (PS_DIM / 4)                    // 50 float4 per patch
#define PATCH_V4 (BC_DIM * P_DIM * V4)           // 18,400,000 float4 outputs
#define MASK_N   (BC_DIM * P_DIM)                // 368,000

#define THREADS_ 512
#define UNROLL_  4
#define CHUNK_   (THREADS_ * UNROLL_)            // 2048 float4 = 32KB per block
#define PATCH_BLOCKS ((PATCH_V4 + CHUNK_ - 1) / CHUNK_)   // 8,985
#define MASK_BLOCKS  ((MASK_N + THREADS_ - 1) / THREADS_) // 719
#define TOTAL_BLOCKS (PATCH_BLOCKS + MASK_BLOCKS)         // 9,704

// Streaming (evict-first) stores: keep the 296MB write stream out of L2 so the
// input (mostly L2-resident across replays, reads ~119MB < 177MB unique) stays.
__device__ __forceinline__ void stcs4(float4* p, float4 v) {
    asm volatile("st.global.cs.v4.f32 [%0], {%1,%2,%3,%4};"
                 :: "l"(p), "f"(v.x), "f"(v.y), "f"(v.z), "f"(v.w) : "memory");
}
__device__ __forceinline__ void stcs1(float* p, float v) {
    asm volatile("st.global.cs.f32 [%0], %1;" :: "l"(p), "f"(v) : "memory");
}

// Compute one float4 of the patches output for flat float4-index `o`.
__device__ __forceinline__ float4 patch_val(const float* __restrict__ x, int o) {
    int v    = o % V4;          // float4 index within patch [0,50)
    int rest = o / V4;
    int p    = rest % P_DIM;    // patch index [0,1000)
    int bc   = rest / P_DIM;    // fused (b,c) [0,368)

    if (p >= ACTUAL_) return make_float4(0.f, 0.f, 0.f, 0.f);

    // src offset = bc*120200 + 150*p + 4*v ; 16B-aligned iff p even.
    const float* src = x + (size_t)bc * T_DIM + p * STRIDE_ + v * 4;
    if ((p & 1) == 0) {
        return *reinterpret_cast<const float4*>(src);
    } else {
        float2 a = *reinterpret_cast<const float2*>(src);
        float2 b = *reinterpret_cast<const float2*>(src + 2);
        return make_float4(a.x, a.y, b.x, b.y);
    }
}

// Single fused launch:
//   blockIdx < PATCH_BLOCKS : block copies one CONTIGUOUS 32KB output window
//     as 4 adjacent coalesced segments per thread (o_k = base + k*blockDim):
//     MLP=4 with preserved locality -> long same-page DRAM bursts.
//   blockIdx >= PATCH_BLOCKS: mask block, hidden under the patch copy.
__global__ void __launch_bounds__(THREADS_) to_patches_fused_kernel(
    const float* __restrict__ x, float* __restrict__ out)
{
    int b = blockIdx.x;

    if (b < PATCH_BLOCKS) {
        int base = b * CHUNK_ + threadIdx.x;
        float4* o = reinterpret_cast<float4*>(out);

        float4 v[UNROLL_];
        bool   has[UNROLL_];
#pragma unroll
        for (int k = 0; k < UNROLL_; k++) {
            int ok = base + k * THREADS_;
            has[k] = (ok < PATCH_V4);
            if (has[k]) v[k] = patch_val(x, ok);
        }
#pragma unroll
        for (int k = 0; k < UNROLL_; k++) {
            int ok = base + k * THREADS_;
            if (has[k]) stcs4(o + ok, v[k]);
        }
    } else {
        // mask[bc, p] = (p < 801) ? 1 : 0
        int m = (b - PATCH_BLOCKS) * THREADS_ + threadIdx.x;
        if (m < MASK_N) {
            int p = m % P_DIM;
            stcs1(out + (size_t)PATCH_V4 * 4 + m, (p < ACTUAL_) ? 1.0f : 0.0f);
        }
    }
}

extern "C" void kernel_launch(void* const* d_in, const int* in_sizes, int n_in,
                              void* d_out, int out_size)
{
    const float* x   = (const float*)d_in[0];
    float*       out = (float*)d_out;

    to_patches_fused_kernel<<<TOTAL_BLOCKS, THREADS_>>>(x, out);
}